// round 8
// baseline (speedup 1.0000x reference)
#include <cuda_runtime.h>
#include <stdint.h>

#define H 2048
#define W 2048
#define KS 11
#define PS 10
#define PAD 5
#define HO 205                 // conv output: floor((2048+10-11)/10)+1
#define OUT 2255               // 205 * (PS+1)
#define CELLS (HO*HO)
#define ROWS_TOTAL (3*OUT)

// Intermediate per-cell result: [3][HO][HO] (+pad for safe over-read)
__device__ float g_mid[3 * HO * HO + 8];

// ---------------------------------------------------------------------------
// Kernel 1: one warp per output cell, direct LDG.
// Warp-uniform interior/border split: interior (99%) loads unconditionally,
// no per-lane masking ALU. 16-bin histogram in packed 8-bit counters,
// argmax via one reduce-max (first-max tie-break like jnp.argmax),
// masked per-channel means.
// ---------------------------------------------------------------------------
__global__ void __launch_bounds__(256) cell_kernel(const float* __restrict__ rgb,
                                                   int base, int limit) {
    const int wid = base + ((blockIdx.x * blockDim.x + threadIdx.x) >> 5);
    if (wid >= limit) return;
    const int lane = threadIdx.x & 31;

    const int oh = wid / HO;
    const int ow = wid - oh * HO;
    const int y0 = oh * PS - PAD;
    const int x0 = ow * PS - PAD;

    const float* __restrict__ rp = rgb;
    const float* __restrict__ gp = rgb + H * W;
    const float* __restrict__ bp = rgb + 2 * H * W;

    float rv[4], gv[4], bv[4];
    int bn[4];                                   // 16 = dead sentinel
    unsigned long long hlo = 0ULL, hhi = 0ULL;   // bins 0-7 / 8-15, 8-bit ctrs
    const bool t3act = (lane < 25);              // 121 = 3*32 + 25

    if ((oh > 0) & (ow > 0)) {
        // ---- interior fast path: every address in-bounds ----
#pragma unroll
        for (int t = 0; t < 4; t++) {
            int p = lane + t * 32;
            if (t == 3) p = p > 120 ? 120 : p;   // clamp dup for lanes >= 25
            const int dy = p / KS;
            const int dx = p - dy * KS;
            const int off = (y0 + dy) * W + (x0 + dx);
            rv[t] = __ldg(rp + off);
            gv[t] = __ldg(gp + off);
            bv[t] = __ldg(bp + off);
        }
#pragma unroll
        for (int t = 0; t < 4; t++) {
            // bin = floor(mean/16) = floor(s * rn(1/48)); exact 2^-4 scaling
            const float s = __fadd_rn(__fadd_rn(rv[t], gv[t]), bv[t]);
            const int bi = (int)(__fmul_rn(s, 0.020833334f));  // 1/48 rn
            const bool a = (t < 3) | t3act;
            bn[t] = a ? bi : 16;
            if (a) {
                const unsigned long long inc = 1ULL << ((bi & 7) * 8);
                if (bi < 8) hlo += inc; else hhi += inc;
            }
        }
    } else {
        // ---- border path: 409 of 42025 cells ----
#pragma unroll
        for (int t = 0; t < 4; t++) {
            const int p = lane + t * 32;
            int dy = p / KS;
            const int dx = p - dy * KS;
            if (dy > 10) dy = 10;
            const bool a = ((t < 3) | t3act) && (y0 + dy >= 0) && (x0 + dx >= 0);
            const int off = (y0 + dy) * W + (x0 + dx);
            rv[t] = a ? __ldg(rp + off) : 0.0f;
            gv[t] = a ? __ldg(gp + off) : 0.0f;
            bv[t] = a ? __ldg(bp + off) : 0.0f;
            const float s = __fadd_rn(__fadd_rn(rv[t], gv[t]), bv[t]);
            const int bi = (int)(__fmul_rn(s, 0.020833334f));
            bn[t] = a ? bi : 16;
            if (a) {
                const unsigned long long inc = 1ULL << ((bi & 7) * 8);
                if (bi < 8) hlo += inc; else hhi += inc;
            }
        }
    }

    // Warp-reduce packed histograms (per-bin totals <= 121 < 256: carry-free)
    const unsigned h0 = __reduce_add_sync(0xffffffffu, (unsigned)hlo);
    const unsigned h1 = __reduce_add_sync(0xffffffffu, (unsigned)(hlo >> 32));
    const unsigned h2 = __reduce_add_sync(0xffffffffu, (unsigned)hhi);
    const unsigned h3 = __reduce_add_sync(0xffffffffu, (unsigned)(hhi >> 32));

    // Lane-parallel argmax: lane (b = lane&15) owns bin b.
    // key = (cnt<<4) | (15-b): ties -> smaller bin wins (jnp.argmax).
    const int b = lane & 15;
    const unsigned hw = (b < 8) ? ((b < 4) ? h0 : h1) : ((b < 12) ? h2 : h3);
    const unsigned cnt = (hw >> ((b & 3) * 8)) & 0xFFu;
    const unsigned key = (cnt << 4) | (unsigned)(15 - b);
    const unsigned kmax = __reduce_max_sync(0xffffffffu, key);
    const int amax = 15 - (int)(kmax & 15u);     // <= 15, so bn==16 never hits
    const float cm = (float)(kmax >> 4);

    // Masked per-channel sums
    float sr = 0.f, sg = 0.f, sb = 0.f;
#pragma unroll
    for (int t = 0; t < 4; t++) {
        if (bn[t] == amax) { sr += rv[t]; sg += gv[t]; sb += bv[t]; }
    }
#pragma unroll
    for (int s = 16; s > 0; s >>= 1) {
        sr += __shfl_xor_sync(0xffffffffu, sr, s);
        sg += __shfl_xor_sync(0xffffffffu, sg, s);
        sb += __shfl_xor_sync(0xffffffffu, sb, s);
    }

    if (lane == 0) {
        const float inv = __frcp_rn(cm);
        g_mid[wid]               = __fmul_rn(sr, inv);
        g_mid[wid + HO * HO]     = __fmul_rn(sg, inv);
        g_mid[wid + 2 * HO * HO] = __fmul_rn(sb, inv);
    }
}

// ---------------------------------------------------------------------------
// Kernel 2: upsample 205x205 -> 2255x2255 per channel (R4 exact — fastest
// measured shape: one 128-thread block per row, magic-div float4 body).
// ---------------------------------------------------------------------------
__global__ void __launch_bounds__(128) upsample_kernel(float* __restrict__ out) {
    const int row = blockIdx.x;            // 0 .. 3*2255-1
    const int tid = threadIdx.x;
    const unsigned ur = (unsigned)row;
    const unsigned c = ur / (unsigned)OUT;
    const unsigned y = ur - c * (unsigned)OUT;
    const unsigned oh = y / 11u;
    const unsigned ii = y - oh * 11u;

    float* __restrict__ orow = out + (size_t)row * OUT;
    const int h = (int)((4u - ((ur * (unsigned)OUT) & 3u)) & 3u);
    const int nv = (OUT - h) >> 2;
    const int nt = OUT - h - nv * 4;
    float4* __restrict__ ov = (float4*)(orow + h);

    if (ii == 10u) {                       // pad row: zeros
        if (tid < h) orow[tid] = 0.0f;
        if (tid >= 4 && tid < 4 + nt) orow[h + nv * 4 + (tid - 4)] = 0.0f;
        const float4 z = make_float4(0.f, 0.f, 0.f, 0.f);
        for (int v = tid; v < nv; v += 128) ov[v] = z;
        return;
    }

    const float* __restrict__ midc = g_mid + c * HO * HO + oh * HO;

    // Scalar head (x <= 2: o=0, j<10 -> always live)
    if (tid < h) orow[tid] = __ldg(midc);
    // Scalar tail (x in 2252..2254)
    if (tid >= 4 && tid < 4 + nt) {
        const unsigned x = (unsigned)(h + nv * 4 + (tid - 4));
        const unsigned o = x / 11u;
        const unsigned j = x - o * 11u;
        orow[x] = (j < 10u) ? __ldg(midc + o) : 0.0f;
    }

    // Vector body: 4 independent magic-divs per float4, no divergence
    for (int v = tid; v < nv; v += 128) {
        const unsigned x0 = (unsigned)(h + v * 4);
        float4 o;
        float* po = &o.x;
#pragma unroll
        for (int k = 0; k < 4; k++) {
            const unsigned x = x0 + (unsigned)k;
            const unsigned ow = x / 11u;
            const unsigned j = x - ow * 11u;
            po[k] = (j < 10u) ? __ldg(midc + ow) : 0.0f;
        }
        ov[v] = o;
    }
}

extern "C" void kernel_launch(void* const* d_in, const int* in_sizes, int n_in,
                              void* d_out, int out_size) {
    const float* rgb = (const float*)d_in[0];
    float* out = (float*)d_out;

    // Cell kernel in two halves -> captured launch (#3 mod 3 == 0) is cellA,
    // giving us the cell profile. Disjoint wid ranges, no interaction.
    const int half = CELLS / 2;                 // 21012
    const int blocksA = (half + 7) / 8;
    const int blocksB = ((CELLS - half) + 7) / 8;
    cell_kernel<<<blocksA, 256>>>(rgb, 0, half);
    cell_kernel<<<blocksB, 256>>>(rgb, half, CELLS);

    upsample_kernel<<<ROWS_TOTAL, 128>>>(out);  // R4 exact
}